// round 14
// baseline (speedup 1.0000x reference)
#include <cuda_runtime.h>
#include <cuda_fp16.h>

// Problem constants
#define Hh   256
#define Gg   1024
#define Tt   50
#define Kk   3
#define FSn  6
#define Bb   4096
#define BT   32            // batch rows per CTA (exact: 4096 = 32*128)
#define NTH  512
#define NWARP 16
#define NBLK (Bb/BT)       // 128 CTAs = one wave

#define KC0  17            // layer0 K = 272 = h(256) | x(4) | pad
#define KC1  32            // layer1 K = 512 = h0 | h1
#define A0S  280           // padded row stride (halves) -> conflict-free ldmatrix
#define A1S  520
#define CS   260           // c-state row stride (floats)

// packed weight sizes (uint4 units): [kc][ntp(64)][lane(32)] * 16B
#define W0SZ (KC0*64*32)   // 34816
#define W1SZ (KC1*64*32)   // 65536
#define WPAD (2*2048)      // 2 extra kc-chunks: depth-2 prefetch overrun landing zone

__device__ uint4  g_w0e[W0SZ + WPAD];
__device__ uint4  g_w1e[W1SZ + WPAD];
__device__ uint4  g_w0d[3*W0SZ + WPAD];
__device__ uint4  g_w1d[3*W1SZ + WPAD];
__device__ float2 g_bias2[8*512];   // 8 segments x 1024 floats, gate-packed col order

struct Smem {
  __half A0[BT*A0S];     // layer0 input rows: [h0(256) | x/inp(4) | pad]
  __half A1[BT*A1S];     // layer1 input rows: [h0_new(256) | h1(256) | pad]
  __half eA1[BT*A1S];    // encoder-final snapshot of A1
  float  c0[BT*CS];
  float  c1[BT*CS];
  float  ec0[BT*CS];
  float  ec1[BT*CS];
  float  inp[BT*2];
  float  logit[BT*Kk];
};

static __device__ __forceinline__ float sigm(float v) {
  return 1.0f / (1.0f + __expf(-v));
}
static __device__ __forceinline__ float tanhx(float v) {
  v = fminf(15.0f, fmaxf(-15.0f, v));
  float e = __expf(2.0f * v);
  return (e - 1.0f) / (e + 1.0f);
}

// ===================== converter: fp32 weights -> f16 B-fragment layout =====================
// Packed element (u32 = 2 f16) index: ((kc*64 + ntp)*32 + lane)*4 + q
//   nt = 2*ntp + (q>>1); n_col = nt*8 + (lane>>2)  (gate-packed: n = unit*4 + gate)
//   j_orig = (n_col&3)*256 + (n_col>>2);  k0 = kc*16 + (lane&3)*2 + (q&1)*8; elems k0, k0+1
__global__ void conv_kernel(
    const float* __restrict__ eWih0, const float* __restrict__ eWhh0,
    const float* __restrict__ ebih0, const float* __restrict__ ebhh0,
    const float* __restrict__ eWih1, const float* __restrict__ eWhh1,
    const float* __restrict__ ebih1, const float* __restrict__ ebhh1,
    const float* __restrict__ dWih0, const float* __restrict__ dWhh0,
    const float* __restrict__ dbih0, const float* __restrict__ dbhh0,
    const float* __restrict__ dWih1, const float* __restrict__ dWhh1,
    const float* __restrict__ dbih1, const float* __restrict__ dbhh1)
{
  const int WU0 = W0SZ*4;          // u32 per layer0 matrix
  const int WU1 = W1SZ*4;
  const int WTOT = WU0 + WU1 + 3*WU0 + 3*WU1;   // 1,605,632
  int idx = blockIdx.x * 256 + threadIdx.x;
  if (idx < WTOT) {
    unsigned* dst; int kind; int mode = 0; int local = idx;
    if (local < WU0) { dst = (unsigned*)g_w0e; kind = 0; }
    else if ((local -= WU0) < WU1) { dst = (unsigned*)g_w1e; kind = 1; }
    else if ((local -= WU1) < 3*WU0) {
      mode = local / WU0; local -= mode*WU0;
      dst = (unsigned*)g_w0d + (size_t)mode*WU0*4/4*4; // == mode*WU0
      dst = (unsigned*)g_w0d + (size_t)mode*WU0; kind = 2;
    } else {
      local -= 3*WU0; mode = local / WU1; local -= mode*WU1;
      dst = (unsigned*)g_w1d + (size_t)mode*WU1; kind = 3;
    }
    int q = local & 3, lane = (local>>2)&31, ntp = (local>>7)&63, kc = local>>13;
    int nt = 2*ntp + (q>>1);
    int ncol = nt*8 + (lane>>2);
    int j = (ncol&3)*256 + (ncol>>2);
    int k0 = kc*16 + (lane&3)*2 + (q&1)*8;     // even
    float v0, v1;
    if (kind == 0) {
      v0 = (k0   < 256) ? eWhh0[j*256 + k0]   : ((k0   < 260) ? eWih0[j*4 + k0-256]   : 0.f);
      v1 = (k0+1 < 256) ? eWhh0[j*256 + k0+1] : ((k0+1 < 260) ? eWih0[j*4 + k0+1-256] : 0.f);
    } else if (kind == 1) {
      v0 = (k0   < 256) ? eWih1[j*256 + k0]   : eWhh1[j*256 + k0-256];
      v1 = (k0+1 < 256) ? eWih1[j*256 + k0+1] : eWhh1[j*256 + k0+1-256];
    } else if (kind == 2) {
      int base = mode*1024 + j;
      v0 = (k0   < 256) ? dWhh0[base*256 + k0]   : ((k0   < 258) ? dWih0[base*2 + k0-256]   : 0.f);
      v1 = (k0+1 < 256) ? dWhh0[base*256 + k0+1] : ((k0+1 < 258) ? dWih0[base*2 + k0+1-256] : 0.f);
    } else {
      int base = mode*1024 + j;
      v0 = (k0   < 256) ? dWih1[base*256 + k0]   : dWhh1[base*256 + k0-256];
      v1 = (k0+1 < 256) ? dWih1[base*256 + k0+1] : dWhh1[base*256 + k0+1-256];
    }
    __half2 h = __floats2half2_rn(v0, v1);
    dst[local] = *(unsigned*)&h;
  } else if (idx < WTOT + 8192) {
    int n = idx - WTOT;
    int seg = n >> 10, col = n & 1023;
    int j = (col&3)*256 + (col>>2);
    float v;
    if      (seg == 0) v = ebih0[j] + ebhh0[j];
    else if (seg == 1) v = ebih1[j] + ebhh1[j];
    else if (seg < 5)  { int m = seg-2; v = dbih0[m*1024+j] + dbhh0[m*1024+j]; }
    else               { int m = seg-5; v = dbih1[m*1024+j] + dbhh1[m*1024+j]; }
    ((float*)g_bias2)[seg*1024 + col] = v;
  }
}

// ===================== MMA primitives =====================
static __device__ __forceinline__ void ldsm4(unsigned* a, unsigned addr) {
  asm volatile("ldmatrix.sync.aligned.m8n8.x4.shared.b16 {%0,%1,%2,%3}, [%4];"
               : "=r"(a[0]),"=r"(a[1]),"=r"(a[2]),"=r"(a[3]) : "r"(addr));
}
static __device__ __forceinline__ void mma16816(float* c, const unsigned* a,
                                                unsigned b0, unsigned b1) {
  asm volatile("mma.sync.aligned.m16n8k16.row.col.f32.f16.f16.f32 "
               "{%0,%1,%2,%3},{%4,%5,%6,%7},{%8,%9},{%0,%1,%2,%3};"
               : "+f"(c[0]),"+f"(c[1]),"+f"(c[2]),"+f"(c[3])
               : "r"(a[0]),"r"(a[1]),"r"(a[2]),"r"(a[3]),"r"(b0),"r"(b1));
}

// Warp w owns n-cols [w*64, w*64+64) = units [w*16, w*16+16), all 32 batch rows.
// C[nt(8)][mh(2)][4]  (64 f32 regs). Depth-2 B prefetch via kc-unroll-2.
template<int KC>
static __device__ __forceinline__ void mma_block(
    const __half* A, int As, const uint4* __restrict__ Wp,
    const float2* __restrict__ bias2, int w, int lane, float C[8][2][4])
{
  #pragma unroll
  for (int nt = 0; nt < 8; nt++) {
    int n0 = (w*8 + nt)*8 + (lane&3)*2;
    float2 bv = bias2[n0>>1];
    #pragma unroll
    for (int mh = 0; mh < 2; mh++) {
      C[nt][mh][0] = bv.x; C[nt][mh][1] = bv.y;
      C[nt][mh][2] = bv.x; C[nt][mh][3] = bv.y;
    }
  }
  int m = lane>>3, r = lane&7;
  unsigned abase = (unsigned)__cvta_generic_to_shared(A);
  unsigned aAddr0 = abase + (unsigned)((((m&1)*8 + r)*As + (m>>1)*8)*2);
  unsigned aAddr1 = aAddr0 + (unsigned)(16*As*2);
  const uint4* p = Wp + (size_t)(w*4)*32 + lane;
  uint4 bufE[4], bufO[4];
  #pragma unroll
  for (int i = 0; i < 4; i++) bufE[i] = p[i*32];
  #pragma unroll
  for (int i = 0; i < 4; i++) bufO[i] = p[2048 + i*32];
  const uint4* pf = p + 2*2048;   // prefetch target (kc+2); overruns land in WPAD
  #pragma unroll 1
  for (int kc = 0; kc + 1 < KC; kc += 2) {
    {  // even sub-iter: consume bufE, refill for kc+2
      unsigned a0[4], a1[4];
      ldsm4(a0, aAddr0); ldsm4(a1, aAddr1);
      aAddr0 += 32; aAddr1 += 32;
      #pragma unroll
      for (int ntp = 0; ntp < 4; ntp++) {
        uint4 bw = bufE[ntp];
        bufE[ntp] = pf[ntp*32];
        mma16816(C[2*ntp  ][0], a0, bw.x, bw.y);
        mma16816(C[2*ntp  ][1], a1, bw.x, bw.y);
        mma16816(C[2*ntp+1][0], a0, bw.z, bw.w);
        mma16816(C[2*ntp+1][1], a1, bw.z, bw.w);
      }
      pf += 2048;
    }
    {  // odd sub-iter: consume bufO, refill for kc+3
      unsigned a0[4], a1[4];
      ldsm4(a0, aAddr0); ldsm4(a1, aAddr1);
      aAddr0 += 32; aAddr1 += 32;
      #pragma unroll
      for (int ntp = 0; ntp < 4; ntp++) {
        uint4 bw = bufO[ntp];
        bufO[ntp] = pf[ntp*32];
        mma16816(C[2*ntp  ][0], a0, bw.x, bw.y);
        mma16816(C[2*ntp  ][1], a1, bw.x, bw.y);
        mma16816(C[2*ntp+1][0], a0, bw.z, bw.w);
        mma16816(C[2*ntp+1][1], a1, bw.z, bw.w);
      }
      pf += 2048;
    }
  }
  if (KC & 1) {   // tail (KC0 = 17)
    unsigned a0[4], a1[4];
    ldsm4(a0, aAddr0); ldsm4(a1, aAddr1);
    #pragma unroll
    for (int ntp = 0; ntp < 4; ntp++) {
      uint4 bw = bufE[ntp];
      mma16816(C[2*ntp  ][0], a0, bw.x, bw.y);
      mma16816(C[2*ntp  ][1], a1, bw.x, bw.y);
      mma16816(C[2*ntp+1][0], a0, bw.z, bw.w);
      mma16816(C[2*ntp+1][1], a1, bw.z, bw.w);
    }
  }
}

// In-register cell update. Gate-packed cols: lanes (l, l^1) jointly hold i,f / g,o
// of the same unit; 2 shfls exchange exactly what each side needs.
static __device__ __forceinline__ void cell_epi(
    float C[8][2][4], int w, int lane, float* __restrict__ cS,
    __half* __restrict__ d1, int d1s, int off1, __half* __restrict__ d2)
{
  const bool even = (lane & 1) == 0;
  const int rbase = (lane>>2) + (even ? 0 : 8);
  const int uoff = (lane&3) >> 1;
  #pragma unroll
  for (int nt = 0; nt < 8; nt++) {
    int u = (w*8 + nt)*2 + uoff;
    #pragma unroll
    for (int mh = 0; mh < 2; mh++) {
      // even sends C[2],C[3] (odd needs them); odd sends C[0],C[1] (even needs them)
      float tA = even ? C[nt][mh][2] : C[nt][mh][0];
      float tB = even ? C[nt][mh][3] : C[nt][mh][1];
      float rA = __shfl_xor_sync(0xffffffffu, tA, 1);
      float rB = __shfl_xor_sync(0xffffffffu, tB, 1);
      float gi, gf, gg, go;
      if (even) { gi = C[nt][mh][0]; gf = C[nt][mh][1]; gg = rA; go = rB; }
      else      { gi = rA; gf = rB; gg = C[nt][mh][2]; go = C[nt][mh][3]; }
      int row = mh*16 + rbase;
      float i_ = sigm(gi), f_ = sigm(gf), g_ = tanhx(gg), o_ = sigm(go);
      float cold = cS[row*CS + u];
      float cn = f_*cold + i_*g_;
      cS[row*CS + u] = cn;
      __half hv = __float2half(o_ * tanhx(cn));
      d1[row*d1s + off1 + u] = hv;
      if (d2) d2[row*A1S + u] = hv;
    }
  }
}

// ===================== main kernel =====================
__global__ void __launch_bounds__(NTH, 1)
mml_kernel(const float* __restrict__ x,
           const float* __restrict__ headW, const float* __restrict__ headB,
           const float* __restrict__ confW, const float* __restrict__ confB,
           float* __restrict__ out)
{
  extern __shared__ char raw[];
  Smem* s = reinterpret_cast<Smem*>(raw);
  const int tid = threadIdx.x, w = tid >> 5, lane = tid & 31;
  const int row0 = blockIdx.x * BT;

  // ---- zero-init A0 (incl pad), A1, c0, c1 ----
  {
    unsigned* a0u = (unsigned*)s->A0;
    unsigned* a1u = (unsigned*)s->A1;
    for (int i = tid; i < BT*A0S/2; i += NTH) a0u[i] = 0u;
    for (int i = tid; i < BT*A1S/2; i += NTH) a1u[i] = 0u;
    for (int i = tid; i < BT*CS; i += NTH) { s->c0[i] = 0.f; s->c1[i] = 0.f; }
  }
  __syncthreads();

  // ================= ENCODER =================
  for (int t = 0; t < Tt; t++) {
    if (tid < 128) {   // stage x_t -> A0 cols 256..259
      int b = tid >> 2, d = tid & 3;
      s->A0[b*A0S + 256 + d] = __float2half(x[(row0 + b)*(Tt*4) + t*4 + d]);
    }
    __syncthreads();
    {
      float C[8][2][4];
      mma_block<KC0>(s->A0, A0S, g_w0e, g_bias2 + 0*512, w, lane, C);
      __syncthreads();
      cell_epi(C, w, lane, s->c0, s->A0, A0S, 0, s->A1);
    }
    __syncthreads();
    {
      float C[8][2][4];
      mma_block<KC1>(s->A1, A1S, g_w1e, g_bias2 + 1*512, w, lane, C);
      __syncthreads();
      cell_epi(C, w, lane, s->c1, s->A1, A1S, 256, (__half*)nullptr);
    }
    __syncthreads();
  }

  // ---- snapshot encoder-final state ----
  {
    unsigned* a1u = (unsigned*)s->A1;
    unsigned* eu  = (unsigned*)s->eA1;
    for (int i = tid; i < BT*A1S/2; i += NTH) eu[i] = a1u[i];
    for (int i = tid; i < BT*CS; i += NTH) { s->ec0[i] = s->c0[i]; s->ec1[i] = s->c1[i]; }
  }
  __syncthreads();

  // ---- confidence head ----
  for (int task = w; task < BT*Kk; task += NWARP) {
    int b = task / Kk, k = task - b*Kk;
    float p = 0.f;
    for (int u = lane; u < Hh; u += 32)
      p += __half2float(s->eA1[b*A1S + 256 + u]) * confW[k*Hh + u];
    #pragma unroll
    for (int off = 16; off; off >>= 1) p += __shfl_down_sync(0xffffffffu, p, off);
    if (lane == 0) s->logit[b*Kk + k] = p + confB[k];
  }
  __syncthreads();
  if (tid < BT) {
    int r = row0 + tid;
    float l0 = s->logit[tid*Kk], l1 = s->logit[tid*Kk+1], l2 = s->logit[tid*Kk+2];
    float m = fmaxf(l0, fmaxf(l1, l2));
    float e0 = __expf(l0-m), e1 = __expf(l1-m), e2 = __expf(l2-m);
    float inv = 1.f / (e0 + e1 + e2);
    float* cp = out + (size_t)Bb*Kk*FSn*2 + (size_t)r*Kk;
    cp[0] = e0*inv; cp[1] = e1*inv; cp[2] = e2*inv;
  }

  // ================= DECODER =================
  for (int km = 0; km < Kk; km++) {
    __syncthreads();
    {  // restore encoder-final state
      unsigned* a1u = (unsigned*)s->A1;
      unsigned* eu  = (unsigned*)s->eA1;
      for (int i = tid; i < BT*A1S/2; i += NTH) a1u[i] = eu[i];
      // A0 cols 0..255 <- h0_final (eA1 lower half), as u32 pairs
      unsigned* a0u = (unsigned*)s->A0;
      for (int i = tid; i < BT*128; i += NTH) {
        int b = i >> 7, c = i & 127;
        a0u[b*(A0S/2) + c] = eu[b*(A1S/2) + c];
      }
      for (int i = tid; i < BT*CS; i += NTH) { s->c0[i] = s->ec0[i]; s->c1[i] = s->ec1[i]; }
      if (tid < BT*2) {
        int b = tid >> 1, d = tid & 1;
        s->inp[tid] = x[(row0 + b)*(Tt*4) + (Tt-1)*4 + d];
      }
    }
    __syncthreads();

    const uint4* w0p = g_w0d + (size_t)km*W0SZ;
    const uint4* w1p = g_w1d + (size_t)km*W1SZ;
    const float2* b0p = g_bias2 + (2+km)*512;
    const float2* b1p = g_bias2 + (5+km)*512;

    for (int t = 0; t < FSn; t++) {
      if (tid < 64) {  // stage feedback input -> A0 cols 256,257 (258,259 hit zero W)
        int b = tid >> 1, d = tid & 1;
        s->A0[b*A0S + 256 + d] = __float2half(s->inp[b*2 + d]);
      }
      __syncthreads();
      {
        float C[8][2][4];
        mma_block<KC0>(s->A0, A0S, w0p, b0p, w, lane, C);
        __syncthreads();
        cell_epi(C, w, lane, s->c0, s->A0, A0S, 0, s->A1);
      }
      __syncthreads();
      {
        float C[8][2][4];
        mma_block<KC1>(s->A1, A1S, w1p, b1p, w, lane, C);
        __syncthreads();
        cell_epi(C, w, lane, s->c1, s->A1, A1S, 256, (__half*)nullptr);
      }
      __syncthreads();
      // head
      for (int task = w; task < BT*2; task += NWARP) {
        int b = task >> 1, d = task & 1;
        float p = 0.f;
        const float* hw = headW + (size_t)(km*2 + d)*Hh;
        for (int u = lane; u < Hh; u += 32)
          p += __half2float(s->A1[b*A1S + 256 + u]) * hw[u];
        #pragma unroll
        for (int off = 16; off; off >>= 1) p += __shfl_down_sync(0xffffffffu, p, off);
        if (lane == 0) {
          p += headB[km*2 + d];
          s->inp[b*2 + d] = p;
          int r = row0 + b;
          out[((((size_t)r*Kk + km)*FSn + t)*2) + d] = p;
        }
      }
      __syncthreads();
    }
  }
}

extern "C" void kernel_launch(void* const* d_in, const int* in_sizes, int n_in,
                              void* d_out, int out_size) {
  (void)in_sizes; (void)n_in; (void)out_size;
  const float* x     = (const float*)d_in[0];
  const float* eWih0 = (const float*)d_in[1];
  const float* eWhh0 = (const float*)d_in[2];
  const float* ebih0 = (const float*)d_in[3];
  const float* ebhh0 = (const float*)d_in[4];
  const float* eWih1 = (const float*)d_in[5];
  const float* eWhh1 = (const float*)d_in[6];
  const float* ebih1 = (const float*)d_in[7];
  const float* ebhh1 = (const float*)d_in[8];
  const float* dWih0 = (const float*)d_in[9];
  const float* dWhh0 = (const float*)d_in[10];
  const float* dbih0 = (const float*)d_in[11];
  const float* dbhh0 = (const float*)d_in[12];
  const float* dWih1 = (const float*)d_in[13];
  const float* dWhh1 = (const float*)d_in[14];
  const float* dbih1 = (const float*)d_in[15];
  const float* dbhh1 = (const float*)d_in[16];
  const float* headW = (const float*)d_in[17];
  const float* headB = (const float*)d_in[18];
  const float* confW = (const float*)d_in[19];
  const float* confB = (const float*)d_in[20];
  float* out = (float*)d_out;

  // 1) pack weights/biases into fragment layout (f16)
  const int WU0 = W0SZ*4, WU1 = W1SZ*4;
  const int total = WU0 + WU1 + 3*WU0 + 3*WU1 + 8192;
  conv_kernel<<<(total + 255)/256, 256>>>(
      eWih0, eWhh0, ebih0, ebhh0, eWih1, eWhh1, ebih1, ebhh1,
      dWih0, dWhh0, dbih0, dbhh0, dWih1, dWhh1, dbih1, dbhh1);

  // 2) persistent LSTM kernel
  const int smem_bytes = (int)sizeof(Smem);
  cudaFuncSetAttribute(mml_kernel, cudaFuncAttributeMaxDynamicSharedMemorySize,
                       smem_bytes);
  mml_kernel<<<NBLK, NTH, smem_bytes>>>(x, headW, headB, confW, confB, out);
}

// round 15
// speedup vs baseline: 1.8874x; 1.8874x over previous
#include <cuda_runtime.h>
#include <cuda_fp16.h>

// Problem constants
#define Hh   256
#define Gg   1024
#define Tt   50
#define Kk   3
#define FSn  6
#define Bb   4096
#define BT   32            // batch rows per CTA (exact: 4096 = 32*128)
#define NTH  512
#define NWARP 16
#define NBLK (Bb/BT)       // 128 CTAs = one wave

#define KC0  17            // layer0 K = 272 = h(256) | x(4) | pad
#define KC1  32            // layer1 K = 512 = h0 | h1
#define A0S  280           // padded row stride (halves) -> conflict-free ldmatrix
#define A1S  520
#define CS   260           // c-state row stride (floats)

// packed weight sizes (uint4 units): [kc][ntp(64)][lane(32)] * 16B
#define W0SZ (KC0*64*32)   // 34816
#define W1SZ (KC1*64*32)   // 65536

__device__ uint4  g_w0e[W0SZ];
__device__ uint4  g_w1e[W1SZ];
__device__ uint4  g_w0d[3*W0SZ];
__device__ uint4  g_w1d[3*W1SZ];
__device__ float2 g_bias2[8*512];   // 8 segments x 1024 floats, gate-packed col order

struct Smem {
  __half A0[BT*A0S];     // layer0 input rows: [h0(256) | x/inp(4) | pad]
  __half A1[BT*A1S];     // layer1 input rows: [h0_new(256) | h1(256) | pad]
  __half eA1[BT*A1S];    // encoder-final snapshot of A1
  float  c0[BT*CS];
  float  c1[BT*CS];
  float  ec0[BT*CS];
  float  ec1[BT*CS];
  float  inp[BT*2];
  float  logit[BT*Kk];
};

// ---- fast activations: single-MUFU tanh; sigmoid via tanh ----
static __device__ __forceinline__ float tanh_fast(float v) {
  float r; asm("tanh.approx.f32 %0, %1;" : "=f"(r) : "f"(v)); return r;
}
static __device__ __forceinline__ float sigm(float v) {
  return fmaf(0.5f, tanh_fast(0.5f * v), 0.5f);
}

// zero-register L1 prefetch of a warp's first B chunk (4 x 512B)
static __device__ __forceinline__ void pf_chunk(const uint4* __restrict__ Wp,
                                                int w, int lane) {
  const uint4* p = Wp + (size_t)(w*4)*32 + lane;
  asm volatile("prefetch.global.L1 [%0];" :: "l"(p));
  asm volatile("prefetch.global.L1 [%0];" :: "l"(p + 32));
  asm volatile("prefetch.global.L1 [%0];" :: "l"(p + 64));
  asm volatile("prefetch.global.L1 [%0];" :: "l"(p + 96));
}

// ===================== converter: fp32 weights -> f16 B-fragment layout =====================
// Packed element (u32 = 2 f16) index: ((kc*64 + ntp)*32 + lane)*4 + q
//   nt = 2*ntp + (q>>1); n_col = nt*8 + (lane>>2)  (gate-packed: n = unit*4 + gate)
//   j_orig = (n_col&3)*256 + (n_col>>2);  k0 = kc*16 + (lane&3)*2 + (q&1)*8; elems k0, k0+1
__global__ void conv_kernel(
    const float* __restrict__ eWih0, const float* __restrict__ eWhh0,
    const float* __restrict__ ebih0, const float* __restrict__ ebhh0,
    const float* __restrict__ eWih1, const float* __restrict__ eWhh1,
    const float* __restrict__ ebih1, const float* __restrict__ ebhh1,
    const float* __restrict__ dWih0, const float* __restrict__ dWhh0,
    const float* __restrict__ dbih0, const float* __restrict__ dbhh0,
    const float* __restrict__ dWih1, const float* __restrict__ dWhh1,
    const float* __restrict__ dbih1, const float* __restrict__ dbhh1)
{
  const int WU0 = W0SZ*4;          // u32 per layer0 matrix
  const int WU1 = W1SZ*4;
  const int WTOT = WU0 + WU1 + 3*WU0 + 3*WU1;   // 1,605,632
  int idx = blockIdx.x * 256 + threadIdx.x;
  if (idx < WTOT) {
    unsigned* dst; int kind; int mode = 0; int local = idx;
    if (local < WU0) { dst = (unsigned*)g_w0e; kind = 0; }
    else if ((local -= WU0) < WU1) { dst = (unsigned*)g_w1e; kind = 1; }
    else if ((local -= WU1) < 3*WU0) {
      mode = local / WU0; local -= mode*WU0;
      dst = (unsigned*)g_w0d + (size_t)mode*WU0; kind = 2;
    } else {
      local -= 3*WU0; mode = local / WU1; local -= mode*WU1;
      dst = (unsigned*)g_w1d + (size_t)mode*WU1; kind = 3;
    }
    int q = local & 3, lane = (local>>2)&31, ntp = (local>>7)&63, kc = local>>13;
    int nt = 2*ntp + (q>>1);
    int ncol = nt*8 + (lane>>2);
    int j = (ncol&3)*256 + (ncol>>2);
    int k0 = kc*16 + (lane&3)*2 + (q&1)*8;     // even
    float v0, v1;
    if (kind == 0) {
      v0 = (k0   < 256) ? eWhh0[j*256 + k0]   : ((k0   < 260) ? eWih0[j*4 + k0-256]   : 0.f);
      v1 = (k0+1 < 256) ? eWhh0[j*256 + k0+1] : ((k0+1 < 260) ? eWih0[j*4 + k0+1-256] : 0.f);
    } else if (kind == 1) {
      v0 = (k0   < 256) ? eWih1[j*256 + k0]   : eWhh1[j*256 + k0-256];
      v1 = (k0+1 < 256) ? eWih1[j*256 + k0+1] : eWhh1[j*256 + k0+1-256];
    } else if (kind == 2) {
      int base = mode*1024 + j;
      v0 = (k0   < 256) ? dWhh0[base*256 + k0]   : ((k0   < 258) ? dWih0[base*2 + k0-256]   : 0.f);
      v1 = (k0+1 < 256) ? dWhh0[base*256 + k0+1] : ((k0+1 < 258) ? dWih0[base*2 + k0+1-256] : 0.f);
    } else {
      int base = mode*1024 + j;
      v0 = (k0   < 256) ? dWih1[base*256 + k0]   : dWhh1[base*256 + k0-256];
      v1 = (k0+1 < 256) ? dWih1[base*256 + k0+1] : dWhh1[base*256 + k0+1-256];
    }
    __half2 h = __floats2half2_rn(v0, v1);
    dst[local] = *(unsigned*)&h;
  } else if (idx < WTOT + 8192) {
    int n = idx - WTOT;
    int seg = n >> 10, col = n & 1023;
    int j = (col&3)*256 + (col>>2);
    float v;
    if      (seg == 0) v = ebih0[j] + ebhh0[j];
    else if (seg == 1) v = ebih1[j] + ebhh1[j];
    else if (seg < 5)  { int m = seg-2; v = dbih0[m*1024+j] + dbhh0[m*1024+j]; }
    else               { int m = seg-5; v = dbih1[m*1024+j] + dbhh1[m*1024+j]; }
    ((float*)g_bias2)[seg*1024 + col] = v;
  }
}

// ===================== MMA primitives =====================
static __device__ __forceinline__ void ldsm4(unsigned* a, unsigned addr) {
  asm volatile("ldmatrix.sync.aligned.m8n8.x4.shared.b16 {%0,%1,%2,%3}, [%4];"
               : "=r"(a[0]),"=r"(a[1]),"=r"(a[2]),"=r"(a[3]) : "r"(addr));
}
static __device__ __forceinline__ void mma16816(float* c, const unsigned* a,
                                                unsigned b0, unsigned b1) {
  asm volatile("mma.sync.aligned.m16n8k16.row.col.f32.f16.f16.f32 "
               "{%0,%1,%2,%3},{%4,%5,%6,%7},{%8,%9},{%0,%1,%2,%3};"
               : "+f"(c[0]),"+f"(c[1]),"+f"(c[2]),"+f"(c[3])
               : "r"(a[0]),"r"(a[1]),"r"(a[2]),"r"(a[3]),"r"(b0),"r"(b1));
}

// Warp w owns n-cols [w*64, w*64+64) = units [w*16, w*16+16), all 32 batch rows.
// C[nt(8)][mh(2)][4]  (64 f32 regs). Single-deep B prefetch (register-neutral).
template<int KC>
static __device__ __forceinline__ void mma_block(
    const __half* A, int As, const uint4* __restrict__ Wp,
    const float2* __restrict__ bias2, int w, int lane, float C[8][2][4])
{
  #pragma unroll
  for (int nt = 0; nt < 8; nt++) {
    int n0 = (w*8 + nt)*8 + (lane&3)*2;
    float2 bv = bias2[n0>>1];
    #pragma unroll
    for (int mh = 0; mh < 2; mh++) {
      C[nt][mh][0] = bv.x; C[nt][mh][1] = bv.y;
      C[nt][mh][2] = bv.x; C[nt][mh][3] = bv.y;
    }
  }
  int m = lane>>3, r = lane&7;
  unsigned abase = (unsigned)__cvta_generic_to_shared(A);
  unsigned aAddr0 = abase + (unsigned)((((m&1)*8 + r)*As + (m>>1)*8)*2);
  unsigned aAddr1 = aAddr0 + (unsigned)(16*As*2);
  const uint4* p = Wp + (size_t)(w*4)*32 + lane;
  uint4 buf[4];
  #pragma unroll
  for (int i = 0; i < 4; i++) buf[i] = p[i*32];
  #pragma unroll 1
  for (int kc = 0; kc < KC; kc++) {
    unsigned a0[4], a1[4];
    ldsm4(a0, aAddr0); ldsm4(a1, aAddr1);
    aAddr0 += 32; aAddr1 += 32;
    const uint4* pn = p + (size_t)((kc+1 < KC) ? (kc+1) : 0) * 2048;
    #pragma unroll
    for (int ntp = 0; ntp < 4; ntp++) {
      uint4 bw = buf[ntp];
      buf[ntp] = pn[ntp*32];            // prefetch next chunk (overlaps mma)
      mma16816(C[2*ntp  ][0], a0, bw.x, bw.y);
      mma16816(C[2*ntp  ][1], a1, bw.x, bw.y);
      mma16816(C[2*ntp+1][0], a0, bw.z, bw.w);
      mma16816(C[2*ntp+1][1], a1, bw.z, bw.w);
    }
  }
}

// In-register cell update (validated in R14). Gate-packed cols: lanes (l, l^1)
// jointly hold i,f / g,o of the same unit; 2 shfls exchange exactly what each needs.
static __device__ __forceinline__ void cell_epi(
    float C[8][2][4], int w, int lane, float* __restrict__ cS,
    __half* __restrict__ d1, int d1s, int off1, __half* __restrict__ d2)
{
  const bool even = (lane & 1) == 0;
  const int rbase = (lane>>2) + (even ? 0 : 8);
  const int uoff = (lane&3) >> 1;
  #pragma unroll
  for (int nt = 0; nt < 8; nt++) {
    int u = (w*8 + nt)*2 + uoff;
    #pragma unroll
    for (int mh = 0; mh < 2; mh++) {
      float tA = even ? C[nt][mh][2] : C[nt][mh][0];
      float tB = even ? C[nt][mh][3] : C[nt][mh][1];
      float rA = __shfl_xor_sync(0xffffffffu, tA, 1);
      float rB = __shfl_xor_sync(0xffffffffu, tB, 1);
      float gi, gf, gg, go;
      if (even) { gi = C[nt][mh][0]; gf = C[nt][mh][1]; gg = rA; go = rB; }
      else      { gi = rA; gf = rB; gg = C[nt][mh][2]; go = C[nt][mh][3]; }
      int row = mh*16 + rbase;
      float i_ = sigm(gi), f_ = sigm(gf);
      float g_ = tanh_fast(gg), o_ = sigm(go);
      float cold = cS[row*CS + u];
      float cn = f_*cold + i_*g_;
      cS[row*CS + u] = cn;
      __half hv = __float2half(o_ * tanh_fast(cn));
      d1[row*d1s + off1 + u] = hv;
      if (d2) d2[row*A1S + u] = hv;
    }
  }
}

// ===================== main kernel =====================
__global__ void __launch_bounds__(NTH, 1)
mml_kernel(const float* __restrict__ x,
           const float* __restrict__ headW, const float* __restrict__ headB,
           const float* __restrict__ confW, const float* __restrict__ confB,
           float* __restrict__ out)
{
  extern __shared__ char raw[];
  Smem* s = reinterpret_cast<Smem*>(raw);
  const int tid = threadIdx.x, w = tid >> 5, lane = tid & 31;
  const int row0 = blockIdx.x * BT;

  // ---- zero-init A0 (incl pad), A1, c0, c1 ----
  {
    unsigned* a0u = (unsigned*)s->A0;
    unsigned* a1u = (unsigned*)s->A1;
    for (int i = tid; i < BT*A0S/2; i += NTH) a0u[i] = 0u;
    for (int i = tid; i < BT*A1S/2; i += NTH) a1u[i] = 0u;
    for (int i = tid; i < BT*CS; i += NTH) { s->c0[i] = 0.f; s->c1[i] = 0.f; }
  }

  // ================= ENCODER (4 barriers/step) =================
  for (int t = 0; t < Tt; t++) {
    if (tid < 128) {   // stage x_t -> A0 cols 256..259 (disjoint from epi1 writes)
      int b = tid >> 2, d = tid & 3;
      s->A0[b*A0S + 256 + d] = __float2half(x[(row0 + b)*(Tt*4) + t*4 + d]);
    }
    pf_chunk(g_w0e, w, lane);
    __syncthreads();                       // s1: stage + epi1(t-1) visible
    float C[8][2][4];
    mma_block<KC0>(s->A0, A0S, g_w0e, g_bias2 + 0*512, w, lane, C);
    __syncthreads();                       // s2: mma0 done reading A0
    cell_epi(C, w, lane, s->c0, s->A0, A0S, 0, s->A1);
    pf_chunk(g_w1e, w, lane);
    __syncthreads();                       // s3: epi0 visible for mma1
    mma_block<KC1>(s->A1, A1S, g_w1e, g_bias2 + 1*512, w, lane, C);
    __syncthreads();                       // s4: mma1 done reading A1
    cell_epi(C, w, lane, s->c1, s->A1, A1S, 256, (__half*)nullptr);
  }
  __syncthreads();   // epi1 of last step visible

  // ---- snapshot encoder-final state ----
  {
    unsigned* a1u = (unsigned*)s->A1;
    unsigned* eu  = (unsigned*)s->eA1;
    for (int i = tid; i < BT*A1S/2; i += NTH) eu[i] = a1u[i];
    for (int i = tid; i < BT*CS; i += NTH) { s->ec0[i] = s->c0[i]; s->ec1[i] = s->c1[i]; }
  }
  __syncthreads();

  // ---- confidence head ----
  for (int task = w; task < BT*Kk; task += NWARP) {
    int b = task / Kk, k = task - b*Kk;
    float p = 0.f;
    for (int u = lane; u < Hh; u += 32)
      p += __half2float(s->eA1[b*A1S + 256 + u]) * confW[k*Hh + u];
    #pragma unroll
    for (int off = 16; off; off >>= 1) p += __shfl_down_sync(0xffffffffu, p, off);
    if (lane == 0) s->logit[b*Kk + k] = p + confB[k];
  }
  __syncthreads();
  if (tid < BT) {
    int r = row0 + tid;
    float l0 = s->logit[tid*Kk], l1 = s->logit[tid*Kk+1], l2 = s->logit[tid*Kk+2];
    float m = fmaxf(l0, fmaxf(l1, l2));
    float e0 = __expf(l0-m), e1 = __expf(l1-m), e2 = __expf(l2-m);
    float inv = 1.f / (e0 + e1 + e2);
    float* cp = out + (size_t)Bb*Kk*FSn*2 + (size_t)r*Kk;
    cp[0] = e0*inv; cp[1] = e1*inv; cp[2] = e2*inv;
  }

  // ================= DECODER =================
  for (int km = 0; km < Kk; km++) {
    __syncthreads();
    {  // restore encoder-final state
      unsigned* a1u = (unsigned*)s->A1;
      unsigned* eu  = (unsigned*)s->eA1;
      for (int i = tid; i < BT*A1S/2; i += NTH) a1u[i] = eu[i];
      unsigned* a0u = (unsigned*)s->A0;
      for (int i = tid; i < BT*128; i += NTH) {
        int b = i >> 7, c = i & 127;
        a0u[b*(A0S/2) + c] = eu[b*(A1S/2) + c];   // h0 cols 0..255
      }
      for (int i = tid; i < BT*CS; i += NTH) { s->c0[i] = s->ec0[i]; s->c1[i] = s->ec1[i]; }
      if (tid < BT*2) {
        int b = tid >> 1, d = tid & 1;
        s->inp[tid] = x[(row0 + b)*(Tt*4) + (Tt-1)*4 + d];
      }
    }
    __syncthreads();

    const uint4* w0p = g_w0d + (size_t)km*W0SZ;
    const uint4* w1p = g_w1d + (size_t)km*W1SZ;
    const float2* b0p = g_bias2 + (2+km)*512;
    const float2* b1p = g_bias2 + (5+km)*512;

    for (int t = 0; t < FSn; t++) {
      if (tid < 64) {  // stage feedback input -> A0 cols 256,257 (258,259 hit zero W)
        int b = tid >> 1, d = tid & 1;
        s->A0[b*A0S + 256 + d] = __float2half(s->inp[b*2 + d]);
      }
      pf_chunk(w0p, w, lane);
      __syncthreads();
      float C[8][2][4];
      mma_block<KC0>(s->A0, A0S, w0p, b0p, w, lane, C);
      __syncthreads();
      cell_epi(C, w, lane, s->c0, s->A0, A0S, 0, s->A1);
      pf_chunk(w1p, w, lane);
      __syncthreads();
      mma_block<KC1>(s->A1, A1S, w1p, b1p, w, lane, C);
      __syncthreads();
      cell_epi(C, w, lane, s->c1, s->A1, A1S, 256, (__half*)nullptr);
      __syncthreads();   // epi1 visible for head
      // head
      for (int task = w; task < BT*2; task += NWARP) {
        int b = task >> 1, d = task & 1;
        float p = 0.f;
        const float* hw = headW + (size_t)(km*2 + d)*Hh;
        for (int u = lane; u < Hh; u += 32)
          p += __half2float(s->A1[b*A1S + 256 + u]) * hw[u];
        #pragma unroll
        for (int off = 16; off; off >>= 1) p += __shfl_down_sync(0xffffffffu, p, off);
        if (lane == 0) {
          p += headB[km*2 + d];
          s->inp[b*2 + d] = p;
          int r = row0 + b;
          out[((((size_t)r*Kk + km)*FSn + t)*2) + d] = p;
        }
      }
      __syncthreads();   // head's inp visible for next staging
    }
  }
}

extern "C" void kernel_launch(void* const* d_in, const int* in_sizes, int n_in,
                              void* d_out, int out_size) {
  (void)in_sizes; (void)n_in; (void)out_size;
  const float* x     = (const float*)d_in[0];
  const float* eWih0 = (const float*)d_in[1];
  const float* eWhh0 = (const float*)d_in[2];
  const float* ebih0 = (const float*)d_in[3];
  const float* ebhh0 = (const float*)d_in[4];
  const float* eWih1 = (const float*)d_in[5];
  const float* eWhh1 = (const float*)d_in[6];
  const float* ebih1 = (const float*)d_in[7];
  const float* ebhh1 = (const float*)d_in[8];
  const float* dWih0 = (const float*)d_in[9];
  const float* dWhh0 = (const float*)d_in[10];
  const float* dbih0 = (const float*)d_in[11];
  const float* dbhh0 = (const float*)d_in[12];
  const float* dWih1 = (const float*)d_in[13];
  const float* dWhh1 = (const float*)d_in[14];
  const float* dbih1 = (const float*)d_in[15];
  const float* dbhh1 = (const float*)d_in[16];
  const float* headW = (const float*)d_in[17];
  const float* headB = (const float*)d_in[18];
  const float* confW = (const float*)d_in[19];
  const float* confB = (const float*)d_in[20];
  float* out = (float*)d_out;

  // 1) pack weights/biases into fragment layout (f16)
  const int WU0 = W0SZ*4, WU1 = W1SZ*4;
  const int total = WU0 + WU1 + 3*WU0 + 3*WU1 + 8192;
  conv_kernel<<<(total + 255)/256, 256>>>(
      eWih0, eWhh0, ebih0, ebhh0, eWih1, eWhh1, ebih1, ebhh1,
      dWih0, dWhh0, dbih0, dbhh0, dWih1, dWhh1, dbih1, dbhh1);

  // 2) persistent LSTM kernel
  const int smem_bytes = (int)sizeof(Smem);
  cudaFuncSetAttribute(mml_kernel, cudaFuncAttributeMaxDynamicSharedMemorySize,
                       smem_bytes);
  mml_kernel<<<NBLK, NTH, smem_bytes>>>(x, headW, headB, confW, confB, out);
}